// round 1
// baseline (speedup 1.0000x reference)
#include <cuda_runtime.h>
#include <cstdint>

// Problem constants (shapes are fixed by the dataset).
#define NN      50000
#define EE      800000
#define KDIM    128
#define OUTDIM  64

// ---------------- device scratch (allocation-free contract) ----------------
__device__ float g_bufA[NN * KDIM];      // SpMM output / GEMM input
__device__ float g_bufB[NN * KDIM];      // GEMM output / SpMM input
__device__ int   g_cnt[NN];              // per-row edge count (in-degree)
__device__ int   g_rowptr[NN + 1];       // CSR row pointers
__device__ int   g_cursor[NN];           // fill cursors
__device__ int   g_adj[EE];              // CSR column (source) indices
__device__ float g_invdeg[NN];           // 1 / (cnt + 1)
__device__ float g_Wc[KDIM * OUTDIM];    // fused W3@W4
__device__ float g_bc[OUTDIM];           // fused b3@W4 + b4
__device__ int   g_is64;                 // edge_index dtype flag

// ---------------- dtype detection ----------------
// If edge_index is int64 (values < 50000), every odd int32 word (high half)
// of the first entries is 0. For int32 data those words are random node ids.
__global__ void detect_kernel(const int* __restrict__ ei) {
    if (threadIdx.x == 0) {
        int allz = 1;
        for (int e = 0; e < 64; e++) {
            if (ei[2 * e + 1] != 0) { allz = 0; break; }
        }
        g_is64 = allz;
    }
}

__global__ void zero_cnt_kernel(int M) {
    int i = blockIdx.x * blockDim.x + threadIdx.x;
    if (i < M) g_cnt[i] = 0;
}

__global__ void count_kernel(const int* __restrict__ ei, int E) {
    int e = blockIdx.x * blockDim.x + threadIdx.x;
    if (e >= E) return;
    int is64 = g_is64;
    int row = is64 ? ei[2 * e] : ei[e];
    atomicAdd(&g_cnt[row], 1);
}

// Single-block exclusive scan over g_cnt -> g_rowptr, also fills cursor/invdeg.
__global__ void scan_kernel(int M) {
    __shared__ int part[1024];
    int t = threadIdx.x;
    int CH = (M + 1023) >> 10;
    int lo = t * CH;
    int hi = lo + CH; if (hi > M) hi = M;

    int s = 0;
    for (int i = lo; i < hi; i++) s += g_cnt[i];
    part[t] = s;
    __syncthreads();

    // Hillis-Steele inclusive scan
    for (int d = 1; d < 1024; d <<= 1) {
        int v = (t >= d) ? part[t - d] : 0;
        __syncthreads();
        part[t] += v;
        __syncthreads();
    }

    int run = (t == 0) ? 0 : part[t - 1];
    for (int i = lo; i < hi; i++) {
        g_rowptr[i] = run;
        g_cursor[i] = run;
        g_invdeg[i] = 1.0f / (float)(g_cnt[i] + 1);
        run += g_cnt[i];
    }
    if (t == 1023) g_rowptr[M] = part[1023];
}

__global__ void fill_kernel(const int* __restrict__ ei, int E) {
    int e = blockIdx.x * blockDim.x + threadIdx.x;
    if (e >= E) return;
    int is64 = g_is64;
    int row, col;
    if (is64) {
        row = ei[2 * e];
        col = ei[2 * E + 2 * e];
    } else {
        row = ei[e];
        col = ei[E + e];
    }
    int pos = atomicAdd(&g_cursor[row], 1);
    g_adj[pos] = col;
}

// ---------------- SpMM: warp per row, gather-only ----------------
// dst[i] = invdeg[i] * (src[i] + sum_{e in row i} src[adj[e]])
__global__ void spmm_kernel(const float* __restrict__ src,
                            float* __restrict__ dst, int M) {
    int warp = (blockIdx.x * blockDim.x + threadIdx.x) >> 5;
    if (warp >= M) return;
    int lane = threadIdx.x & 31;

    const float4* s4 = (const float4*)src;
    size_t rowbase = (size_t)warp * (KDIM / 4);

    float4 a = s4[rowbase + lane];  // self loop
    float ax = a.x, ay = a.y, az = a.z, aw = a.w;

    int e   = g_rowptr[warp];
    int end = g_rowptr[warp + 1];

    for (; e + 4 <= end; e += 4) {
        int j0 = g_adj[e], j1 = g_adj[e + 1], j2 = g_adj[e + 2], j3 = g_adj[e + 3];
        float4 v0 = s4[(size_t)j0 * (KDIM / 4) + lane];
        float4 v1 = s4[(size_t)j1 * (KDIM / 4) + lane];
        float4 v2 = s4[(size_t)j2 * (KDIM / 4) + lane];
        float4 v3 = s4[(size_t)j3 * (KDIM / 4) + lane];
        ax += v0.x + v1.x + v2.x + v3.x;
        ay += v0.y + v1.y + v2.y + v3.y;
        az += v0.z + v1.z + v2.z + v3.z;
        aw += v0.w + v1.w + v2.w + v3.w;
    }
    for (; e < end; e++) {
        int j = g_adj[e];
        float4 v = s4[(size_t)j * (KDIM / 4) + lane];
        ax += v.x; ay += v.y; az += v.z; aw += v.w;
    }

    float inv = g_invdeg[warp];
    float4 o;
    o.x = ax * inv; o.y = ay * inv; o.z = az * inv; o.w = aw * inv;
    ((float4*)dst)[rowbase + lane] = o;
}

// ---------------- fused post_mp weight precompute ----------------
// g_Wc = W3 @ W4 (128x64), g_bc = b3 @ W4 + b4
__global__ void wc_kernel(const float* __restrict__ W3, const float* __restrict__ b3,
                          const float* __restrict__ W4, const float* __restrict__ b4) {
    int blk = blockIdx.x;
    int c = threadIdx.x;  // 64 threads
    if (blk < KDIM) {
        float s = 0.0f;
        for (int m = 0; m < KDIM; m++)
            s += W3[blk * KDIM + m] * W4[m * OUTDIM + c];
        g_Wc[blk * OUTDIM + c] = s;
    } else {
        float s = b4[c];
        for (int m = 0; m < KDIM; m++)
            s += b3[m] * W4[m * OUTDIM + c];
        g_bc[c] = s;
    }
}

// ---------------- GEMM: C[M,NOUT] = A[M,128] @ W[128,NOUT] + bias ----------------
// 256 threads, per-thread 8 rows x 4 cols register tile, W + A tile in SMEM.
template <int NOUT, bool RELU>
__global__ void gemm_kernel(const float* __restrict__ A, const float* __restrict__ W,
                            const float* __restrict__ bias, float* __restrict__ C,
                            int M) {
    constexpr int K   = KDIM;
    constexpr int CT  = NOUT / 4;    // col-thread groups (32 or 16)
    constexpr int RT  = 256 / CT;    // row-thread groups (8 or 16)
    constexpr int RPT = 8;           // rows per thread
    constexpr int TM  = RT * RPT;    // 64 or 128 rows per block

    extern __shared__ float sm[];
    float* Ws = sm;                  // K * NOUT
    float* As = sm + K * NOUT;       // TM * K

    int m0 = blockIdx.x * TM;

    // stage W
    for (int i = threadIdx.x; i < K * NOUT / 4; i += 256)
        ((float4*)Ws)[i] = ((const float4*)W)[i];
    // stage A tile (guard tail rows)
    for (int i = threadIdx.x; i < TM * K / 4; i += 256) {
        int r  = i >> 5;             // K/4 == 32 float4 per row
        int gr = m0 + r;
        ((float4*)As)[i] = (gr < M) ? ((const float4*)A)[(size_t)gr * 32 + (i & 31)]
                                    : make_float4(0.f, 0.f, 0.f, 0.f);
    }
    __syncthreads();

    int ct = threadIdx.x % CT;
    int rt = threadIdx.x / CT;
    int c0 = ct * 4;

    float acc[RPT][4];
#pragma unroll
    for (int r = 0; r < RPT; r++) {
        acc[r][0] = 0.f; acc[r][1] = 0.f; acc[r][2] = 0.f; acc[r][3] = 0.f;
    }

    const float* arow = As + (rt * RPT) * K;

#pragma unroll 4
    for (int k = 0; k < K; k++) {
        float4 w = *(const float4*)&Ws[k * NOUT + c0];
#pragma unroll
        for (int r = 0; r < RPT; r++) {
            float a = arow[r * K + k];
            acc[r][0] += a * w.x;
            acc[r][1] += a * w.y;
            acc[r][2] += a * w.z;
            acc[r][3] += a * w.w;
        }
    }

    float4 bv = *(const float4*)&bias[c0];
#pragma unroll
    for (int r = 0; r < RPT; r++) {
        int gr = m0 + rt * RPT + r;
        if (gr < M) {
            float4 o;
            o.x = acc[r][0] + bv.x;
            o.y = acc[r][1] + bv.y;
            o.z = acc[r][2] + bv.z;
            o.w = acc[r][3] + bv.w;
            if (RELU) {
                o.x = fmaxf(o.x, 0.f); o.y = fmaxf(o.y, 0.f);
                o.z = fmaxf(o.z, 0.f); o.w = fmaxf(o.w, 0.f);
            }
            *(float4*)&C[(size_t)gr * NOUT + c0] = o;
        }
    }
}

// ---------------- host launch ----------------
extern "C" void kernel_launch(void* const* d_in, const int* in_sizes, int n_in,
                              void* d_out, int out_size) {
    const float* x  = (const float*)d_in[0];
    const int*   ei = (const int*)d_in[1];
    const float* W1 = (const float*)d_in[2];
    const float* b1 = (const float*)d_in[3];
    const float* W2 = (const float*)d_in[4];
    const float* b2 = (const float*)d_in[5];
    const float* W3 = (const float*)d_in[6];
    const float* b3 = (const float*)d_in[7];
    const float* W4 = (const float*)d_in[8];
    const float* b4 = (const float*)d_in[9];
    float* out = (float*)d_out;

    int M = in_sizes[0] / KDIM;   // 50000
    int E = in_sizes[1] / 2;      // 800000 (element count of (2,E) either dtype)

    // device-global addresses for scratch buffers
    float *bufA, *bufB, *Wc, *bc;
    cudaGetSymbolAddress((void**)&bufA, g_bufA);
    cudaGetSymbolAddress((void**)&bufB, g_bufB);
    cudaGetSymbolAddress((void**)&Wc, g_Wc);
    cudaGetSymbolAddress((void**)&bc, g_bc);

    // >48KB dynamic smem for GEMM kernels
    constexpr int SMEM_BYTES = (KDIM * KDIM + 64 * KDIM) * 4;          // 96KB (NOUT=128)
    constexpr int SMEM_BYTES64 = (KDIM * OUTDIM + 128 * KDIM) * 4;     // 96KB (NOUT=64)
    cudaFuncSetAttribute(gemm_kernel<128, true>,
                         cudaFuncAttributeMaxDynamicSharedMemorySize, SMEM_BYTES);
    cudaFuncSetAttribute(gemm_kernel<64, false>,
                         cudaFuncAttributeMaxDynamicSharedMemorySize, SMEM_BYTES64);

    // ---- CSR build ----
    detect_kernel<<<1, 32>>>(ei);
    zero_cnt_kernel<<<(M + 255) / 256, 256>>>(M);
    count_kernel<<<(E + 511) / 512, 512>>>(ei, E);
    scan_kernel<<<1, 1024>>>(M);
    fill_kernel<<<(E + 511) / 512, 512>>>(ei, E);

    // fused post_mp weights (independent; overlap with early work)
    wc_kernel<<<KDIM + 1, OUTDIM>>>(W3, b3, W4, b4);

    int spmm_blocks = (M * 32 + 255) / 256;

    // layer 1: propagate(x) -> relu(@W1 + b1)
    spmm_kernel<<<spmm_blocks, 256>>>(x, bufA, M);
    gemm_kernel<128, true><<<(M + 63) / 64, 256, SMEM_BYTES>>>(bufA, W1, b1, bufB, M);

    // layer 2: propagate(h1) -> relu(@W2 + b2)
    spmm_kernel<<<spmm_blocks, 256>>>(bufB, bufA, M);
    gemm_kernel<128, true><<<(M + 63) / 64, 256, SMEM_BYTES>>>(bufA, W2, b2, bufB, M);

    // post_mp fused: out = h2 @ Wc + bc
    gemm_kernel<64, false><<<(M + 127) / 128, 256, SMEM_BYTES64>>>(bufB, Wc, bc, out, M);
}

// round 2
// speedup vs baseline: 1.1381x; 1.1381x over previous
#include <cuda_runtime.h>
#include <cstdint>

#define NN      50000
#define EE      800000
#define KDIM    128
#define OUTDIM  64
#define CHUNK   512
#define MAXNB   128   // >= ceil(NN/CHUNK) = 98

typedef unsigned long long u64;

// ---------------- device scratch (allocation-free contract) ----------------
__device__ float g_bufA[NN * KDIM];
__device__ float g_bufB[NN * KDIM];
__device__ int   g_cnt[NN];
__device__ int   g_rowptr[NN + 1];
__device__ int   g_cursor[NN];
__device__ int   g_adj[EE];
__device__ float g_invdeg[NN];
__device__ float g_Wc[KDIM * OUTDIM];
__device__ float g_bc[OUTDIM];
__device__ int   g_is64;
__device__ int   g_bsum[MAXNB];
__device__ int   g_boff[MAXNB];

// ---------------- packed fp32 helpers (sm_103a FFMA2) ----------------
__device__ __forceinline__ u64 pack2(float lo, float hi) {
    u64 r; asm("mov.b64 %0, {%1, %2};" : "=l"(r) : "f"(lo), "f"(hi)); return r;
}
__device__ __forceinline__ void unpack2(u64 v, float& lo, float& hi) {
    asm("mov.b64 {%0, %1}, %2;" : "=f"(lo), "=f"(hi) : "l"(v));
}
__device__ __forceinline__ void ffma2(u64& d, u64 a, u64 b) {
    asm("fma.rn.f32x2 %0, %1, %2, %3;" : "=l"(d) : "l"(a), "l"(b), "l"(d));
}

// ---------------- dtype detection ----------------
__global__ void detect_kernel(const int* __restrict__ ei) {
    if (threadIdx.x == 0) {
        int allz = 1;
        for (int e = 0; e < 64; e++) {
            if (ei[2 * e + 1] != 0) { allz = 0; break; }
        }
        g_is64 = allz;
    }
}

__global__ void zero_cnt_kernel(int M) {
    int i = blockIdx.x * blockDim.x + threadIdx.x;
    if (i < M) g_cnt[i] = 0;
}

__global__ void count_kernel(const int* __restrict__ ei, int E) {
    int e = blockIdx.x * blockDim.x + threadIdx.x;
    if (e >= E) return;
    int row = g_is64 ? ei[2 * e] : ei[e];
    atomicAdd(&g_cnt[row], 1);
}

// ---------------- parallel 3-phase scan ----------------
__global__ void bsum_kernel(int M) {
    __shared__ int sh[256];
    int b = blockIdx.x, t = threadIdx.x;
    int i0 = b * CHUNK + t, i1 = i0 + 256;
    int s = 0;
    if (i0 < M) s += g_cnt[i0];
    if (i1 < M) s += g_cnt[i1];
    sh[t] = s; __syncthreads();
    for (int d = 128; d > 0; d >>= 1) {
        if (t < d) sh[t] += sh[t + d];
        __syncthreads();
    }
    if (t == 0) g_bsum[b] = sh[0];
}

__global__ void bscan_kernel(int NB, int M) {
    __shared__ int sh[MAXNB];
    int t = threadIdx.x;
    int v = (t < NB) ? g_bsum[t] : 0;
    sh[t] = v; __syncthreads();
    for (int d = 1; d < MAXNB; d <<= 1) {
        int u = (t >= d) ? sh[t - d] : 0;
        __syncthreads();
        sh[t] += u;
        __syncthreads();
    }
    if (t < NB) g_boff[t] = sh[t] - v;
    if (t == MAXNB - 1) g_rowptr[M] = sh[MAXNB - 1];
}

__global__ void emit_kernel(int M) {
    __shared__ int sh[256];
    int b = blockIdx.x, t = threadIdx.x;
    int base = g_boff[b];
    int i0 = b * CHUNK + 2 * t, i1 = i0 + 1;
    int v0 = (i0 < M) ? g_cnt[i0] : 0;
    int v1 = (i1 < M) ? g_cnt[i1] : 0;
    int s = v0 + v1;
    sh[t] = s; __syncthreads();
    for (int d = 1; d < 256; d <<= 1) {
        int u = (t >= d) ? sh[t - d] : 0;
        __syncthreads();
        sh[t] += u;
        __syncthreads();
    }
    int ex = base + sh[t] - s;
    if (i0 < M) {
        g_rowptr[i0] = ex; g_cursor[i0] = ex;
        g_invdeg[i0] = 1.0f / (float)(v0 + 1);
    }
    if (i1 < M) {
        g_rowptr[i1] = ex + v0; g_cursor[i1] = ex + v0;
        g_invdeg[i1] = 1.0f / (float)(v1 + 1);
    }
}

__global__ void fill_kernel(const int* __restrict__ ei, int E) {
    int e = blockIdx.x * blockDim.x + threadIdx.x;
    if (e >= E) return;
    int row, col;
    if (g_is64) {
        row = ei[2 * e];
        col = ei[2 * E + 2 * e];
    } else {
        row = ei[e];
        col = ei[E + e];
    }
    int pos = atomicAdd(&g_cursor[row], 1);
    g_adj[pos] = col;
}

// ---------------- SpMM: warp per row, gather-only, 8-wide MLP ----------------
__global__ void spmm_kernel(const float* __restrict__ src,
                            float* __restrict__ dst, int M) {
    int warp = (blockIdx.x * blockDim.x + threadIdx.x) >> 5;
    if (warp >= M) return;
    int lane = threadIdx.x & 31;

    const float4* s4 = (const float4*)src;
    size_t rowbase = (size_t)warp * (KDIM / 4);

    float4 a = s4[rowbase + lane];
    float ax = a.x, ay = a.y, az = a.z, aw = a.w;

    int e   = g_rowptr[warp];
    int end = g_rowptr[warp + 1];

    for (; e + 8 <= end; e += 8) {
        float4 v[8];
#pragma unroll
        for (int q = 0; q < 8; q++) {
            int j = g_adj[e + q];
            v[q] = s4[(size_t)j * (KDIM / 4) + lane];
        }
#pragma unroll
        for (int q = 0; q < 8; q++) {
            ax += v[q].x; ay += v[q].y; az += v[q].z; aw += v[q].w;
        }
    }
    for (; e < end; e++) {
        int j = g_adj[e];
        float4 v = s4[(size_t)j * (KDIM / 4) + lane];
        ax += v.x; ay += v.y; az += v.z; aw += v.w;
    }

    float inv = g_invdeg[warp];
    float4 o;
    o.x = ax * inv; o.y = ay * inv; o.z = az * inv; o.w = aw * inv;
    ((float4*)dst)[rowbase + lane] = o;
}

// ---------------- fused post_mp weight precompute ----------------
__global__ void wc_kernel(const float* __restrict__ W3, const float* __restrict__ b3,
                          const float* __restrict__ W4, const float* __restrict__ b4) {
    int blk = blockIdx.x;
    int c = threadIdx.x;
    if (blk < KDIM) {
        float s = 0.0f;
        for (int m = 0; m < KDIM; m++)
            s += W3[blk * KDIM + m] * W4[m * OUTDIM + c];
        g_Wc[blk * OUTDIM + c] = s;
    } else {
        float s = b4[c];
        for (int m = 0; m < KDIM; m++)
            s += b3[m] * W4[m * OUTDIM + c];
        g_bc[c] = s;
    }
}

// ---------------- GEMM with packed FFMA2: C = A[M,128] @ W[128,NOUT] + bias ----------------
// 256 threads; 8 cols/thread as 4 f32x2 pairs, RPT rows/thread.
template <int NOUT, bool RELU>
__global__ void gemm_kernel(const float* __restrict__ A, const float* __restrict__ W,
                            const float* __restrict__ bias, float* __restrict__ C,
                            int M) {
    constexpr int K   = KDIM;
    constexpr int CPT = 8;
    constexpr int CT  = NOUT / CPT;   // 16 (NOUT=128) or 8 (NOUT=64)
    constexpr int RT  = 256 / CT;     // 16 or 32
    constexpr int RPT = (NOUT == 128) ? 4 : 4;
    constexpr int TM  = RT * RPT;     // 64 or 128

    extern __shared__ float sm[];
    float* Ws = sm;                   // K * NOUT
    float* As = sm + K * NOUT;        // TM * K

    int m0 = blockIdx.x * TM;

    for (int i = threadIdx.x; i < K * NOUT / 4; i += 256)
        ((float4*)Ws)[i] = ((const float4*)W)[i];
    for (int i = threadIdx.x; i < TM * K / 4; i += 256) {
        int r  = i >> 5;
        int gr = m0 + r;
        ((float4*)As)[i] = (gr < M) ? ((const float4*)A)[(size_t)gr * 32 + (i & 31)]
                                    : make_float4(0.f, 0.f, 0.f, 0.f);
    }
    __syncthreads();

    int ct = threadIdx.x % CT;
    int rt = threadIdx.x / CT;
    int c0 = ct * CPT;

    u64 acc[RPT][4];
#pragma unroll
    for (int r = 0; r < RPT; r++)
#pragma unroll
        for (int p = 0; p < 4; p++) acc[r][p] = 0ull;

    const float* arow = As + (rt * RPT) * K;

#pragma unroll 4
    for (int k = 0; k < K; k++) {
        ulonglong2 wA = *(const ulonglong2*)&Ws[k * NOUT + c0];      // cols c0..c3
        ulonglong2 wB = *(const ulonglong2*)&Ws[k * NOUT + c0 + 4];  // cols c4..c7
#pragma unroll
        for (int r = 0; r < RPT; r++) {
            float a = arow[r * K + k];
            u64 aa = pack2(a, a);
            ffma2(acc[r][0], aa, wA.x);
            ffma2(acc[r][1], aa, wA.y);
            ffma2(acc[r][2], aa, wB.x);
            ffma2(acc[r][3], aa, wB.y);
        }
    }

    float4 bv0 = *(const float4*)&bias[c0];
    float4 bv1 = *(const float4*)&bias[c0 + 4];

#pragma unroll
    for (int r = 0; r < RPT; r++) {
        int gr = m0 + rt * RPT + r;
        if (gr >= M) continue;
        float o[8];
        unpack2(acc[r][0], o[0], o[1]);
        unpack2(acc[r][1], o[2], o[3]);
        unpack2(acc[r][2], o[4], o[5]);
        unpack2(acc[r][3], o[6], o[7]);
        o[0] += bv0.x; o[1] += bv0.y; o[2] += bv0.z; o[3] += bv0.w;
        o[4] += bv1.x; o[5] += bv1.y; o[6] += bv1.z; o[7] += bv1.w;
        if (RELU) {
#pragma unroll
            for (int p = 0; p < 8; p++) o[p] = fmaxf(o[p], 0.f);
        }
        float4 s0 = make_float4(o[0], o[1], o[2], o[3]);
        float4 s1 = make_float4(o[4], o[5], o[6], o[7]);
        *(float4*)&C[(size_t)gr * NOUT + c0]     = s0;
        *(float4*)&C[(size_t)gr * NOUT + c0 + 4] = s1;
    }
}

// ---------------- host launch ----------------
extern "C" void kernel_launch(void* const* d_in, const int* in_sizes, int n_in,
                              void* d_out, int out_size) {
    const float* x  = (const float*)d_in[0];
    const int*   ei = (const int*)d_in[1];
    const float* W1 = (const float*)d_in[2];
    const float* b1 = (const float*)d_in[3];
    const float* W2 = (const float*)d_in[4];
    const float* b2 = (const float*)d_in[5];
    const float* W3 = (const float*)d_in[6];
    const float* b3 = (const float*)d_in[7];
    const float* W4 = (const float*)d_in[8];
    const float* b4 = (const float*)d_in[9];
    float* out = (float*)d_out;

    int M = in_sizes[0] / KDIM;   // 50000
    int E = in_sizes[1] / 2;      // 800000
    int NB = (M + CHUNK - 1) / CHUNK;

    float *bufA, *bufB, *Wc, *bc;
    cudaGetSymbolAddress((void**)&bufA, g_bufA);
    cudaGetSymbolAddress((void**)&bufB, g_bufB);
    cudaGetSymbolAddress((void**)&Wc, g_Wc);
    cudaGetSymbolAddress((void**)&bc, g_bc);

    // smem: NOUT=128 -> Ws 64KB + As(TM=64) 32KB = 96KB
    //       NOUT=64  -> Ws 32KB + As(TM=128) 64KB = 96KB
    constexpr int SMEM128 = (KDIM * KDIM + 64 * KDIM) * 4;
    constexpr int SMEM64  = (KDIM * OUTDIM + 128 * KDIM) * 4;
    cudaFuncSetAttribute(gemm_kernel<128, true>,
                         cudaFuncAttributeMaxDynamicSharedMemorySize, SMEM128);
    cudaFuncSetAttribute(gemm_kernel<64, false>,
                         cudaFuncAttributeMaxDynamicSharedMemorySize, SMEM64);

    // ---- CSR build ----
    detect_kernel<<<1, 32>>>(ei);
    zero_cnt_kernel<<<(M + 255) / 256, 256>>>(M);
    count_kernel<<<(E + 511) / 512, 512>>>(ei, E);
    bsum_kernel<<<NB, 256>>>(M);
    bscan_kernel<<<1, MAXNB>>>(NB, M);
    emit_kernel<<<NB, 256>>>(M);
    fill_kernel<<<(E + 511) / 512, 512>>>(ei, E);

    wc_kernel<<<KDIM + 1, OUTDIM>>>(W3, b3, W4, b4);

    int spmm_blocks = (M * 32 + 255) / 256;

    spmm_kernel<<<spmm_blocks, 256>>>(x, bufA, M);
    gemm_kernel<128, true><<<(M + 63) / 64, 256, SMEM128>>>(bufA, W1, b1, bufB, M);

    spmm_kernel<<<spmm_blocks, 256>>>(bufB, bufA, M);
    gemm_kernel<128, true><<<(M + 63) / 64, 256, SMEM128>>>(bufA, W2, b2, bufB, M);

    gemm_kernel<64, false><<<(M + 127) / 128, 256, SMEM64>>>(bufB, Wc, bc, out, M);
}